// round 2
// baseline (speedup 1.0000x reference)
#include <cuda_runtime.h>

#define Bn 32
#define Sn 512
#define In 1024
#define Hn 1024
#define Ln 3
#define On 1024
#define NCTA 128
#define NTHR 512
#define PADR 130   // ull per 32-batch row in shared tile (pad keeps banks clean, 16B align)

typedef unsigned long long ull;

// Scratch: double-buffered hidden state per layer (rewritten from h0 every launch).
__device__ float g_hbuf[2][Ln][Bn][Hn];
__device__ unsigned g_cnt = 0;
__device__ unsigned g_gen = 0;

// ---------------- packed f32x2 helpers (pairing dimension = K) ----------------
__device__ __forceinline__ void fma2(ull& a, ull w, ull i) {
    asm("fma.rn.f32x2 %0, %1, %2, %0;" : "+l"(a) : "l"(w), "l"(i));
}
__device__ __forceinline__ void fadd2(ull& a, ull b) {
    asm("add.rn.f32x2 %0, %0, %1;" : "+l"(a) : "l"(b));
}
__device__ __forceinline__ float hsum(ull v) {
    float lo, hi;
    asm("mov.b64 {%0,%1}, %2;" : "=f"(lo), "=f"(hi) : "l"(v));
    return lo + hi;
}

// ---------------- software grid barrier ----------------
__device__ __forceinline__ void gsync() {
    __threadfence();
    __syncthreads();
    if (threadIdx.x == 0) {
        unsigned gen = *((volatile unsigned*)&g_gen);
        unsigned t = atomicAdd(&g_cnt, 1u);
        if (t == gridDim.x - 1) {
            g_cnt = 0;
            __threadfence();
            *((volatile unsigned*)&g_gen) = gen + 1;
        } else {
            while (*((volatile unsigned*)&g_gen) == gen) { }
        }
        __threadfence();
    }
    __syncthreads();
}

// ---------------- tile staging: LDG first, STS deferred (hides global latency) ----
struct Stage { float4 v[4]; };

__device__ __forceinline__ Stage ld_tile(const float* __restrict__ src,
                                         size_t stride, int col0) {
    Stage s;
    int tid = threadIdx.x;
#pragma unroll
    for (int r = 0; r < 4; ++r) {
        int u = tid + r * NTHR;
        int b = u >> 6;          // batch row 0..31
        int q = u & 63;          // float4 index within 256-float row slice
        s.v[r] = *reinterpret_cast<const float4*>(src + (size_t)b * stride + col0 + q * 4);
    }
    return s;
}

__device__ __forceinline__ void st_tile(ull* __restrict__ sh, const Stage& s) {
    int tid = threadIdx.x;
#pragma unroll
    for (int r = 0; r < 4; ++r) {
        int u = tid + r * NTHR;
        int b = u >> 6;
        int q = u & 63;
        *reinterpret_cast<float4*>(sh + b * PADR + q * 2) = s.v[r];
    }
}

// 3-gate accumulation over this thread's 32-k slice of a 256-k tile.
__device__ __forceinline__ void compute3(const ull* __restrict__ sh,
                                         const float* __restrict__ w0,
                                         const float* __restrict__ w1,
                                         const float* __restrict__ w2,
                                         int kh, int bq,
                                         ull* a0, ull* a1, ull* a2) {
    const int kbase = kh * 16;  // ull offset inside row
#pragma unroll
    for (int g = 0; g < 8; ++g) {
        const int kc = kh * 32 + g * 4;  // float offset inside tile
        ulonglong2 wz = *reinterpret_cast<const ulonglong2*>(w0 + kc);
        ulonglong2 wr = *reinterpret_cast<const ulonglong2*>(w1 + kc);
        ulonglong2 wg = *reinterpret_cast<const ulonglong2*>(w2 + kc);
#pragma unroll
        for (int b = 0; b < 4; ++b) {
            const ull* sp = sh + (bq * 4 + b) * PADR + kbase + g * 2;
            ull i0 = sp[0];
            ull i1 = sp[1];
            fma2(a0[b], wz.x, i0); fma2(a0[b], wz.y, i1);
            fma2(a1[b], wr.x, i0); fma2(a1[b], wr.y, i1);
            fma2(a2[b], wg.x, i0); fma2(a2[b], wg.y, i1);
        }
    }
}

__device__ __forceinline__ void compute1(const ull* __restrict__ sh,
                                         const float* __restrict__ w0,
                                         int kh, int bq, ull* a0) {
    const int kbase = kh * 16;
#pragma unroll
    for (int g = 0; g < 8; ++g) {
        const int kc = kh * 32 + g * 4;
        ulonglong2 wz = *reinterpret_cast<const ulonglong2*>(w0 + kc);
#pragma unroll
        for (int b = 0; b < 4; ++b) {
            const ull* sp = sh + (bq * 4 + b) * PADR + kbase + g * 2;
            ull i0 = sp[0];
            ull i1 = sp[1];
            fma2(a0[b], wz.x, i0); fma2(a0[b], wz.y, i1);
        }
    }
}

__global__ void __launch_bounds__(NTHR, 1)
gru_persistent(const float* __restrict__ x, const float* __restrict__ h0,
               const float* __restrict__ Wzi, const float* __restrict__ Wzh,
               const float* __restrict__ bzh, const float* __restrict__ Wri,
               const float* __restrict__ Wrh, const float* __restrict__ brh,
               const float* __restrict__ Wgi, const float* __restrict__ Wgh,
               const float* __restrict__ bgh, const float* __restrict__ Wout,
               const float* __restrict__ bout, float* __restrict__ out) {
    extern __shared__ ull smem[];
    ull* shTa = smem;                   // tile buffer 0: 32*PADR ull
    ull* shTb = smem + 32 * PADR;       // tile buffer 1
    ull (*shRed)[16] = reinterpret_cast<ull(*)[16]>(smem + 2 * 32 * PADR);  // [7*64][16]

    const int tid = threadIdx.x;
    const int ns = tid & 7;            // n slot (8 per CTA)
    const int bq = (tid >> 3) & 7;     // batch quad: batches bq*4 .. bq*4+3
    const int kh = tid >> 6;           // k-split group (8): 32 k per 256-k tile
    const int slot = tid & 63;         // (bq, ns) output slot
    const int n = blockIdx.x * 8 + ns; // output column

    // init hidden buffer 0 from h0 (B, L, H)
    for (int i = blockIdx.x * NTHR + tid; i < Ln * Bn * Hn; i += NCTA * NTHR) {
        int hh = i % Hn;
        int b_ = (i / Hn) % Bn;
        int l_ = i / (Hn * Bn);
        g_hbuf[0][l_][b_][hh] = h0[((size_t)b_ * Ln + l_) * Hn + hh];
    }
    gsync();

    int p = 0;
#pragma unroll 1
    for (int t = 0; t < Sn; ++t) {
        const int q = p ^ 1;
#pragma unroll 1
        for (int l = 0; l < Ln; ++l) {
            const float* srcI = (l == 0) ? (x + (size_t)t * In)
                                         : &g_hbuf[q][l - 1][0][0];
            const size_t strI = (l == 0) ? (size_t)Sn * In : (size_t)Hn;
            const float* srcH = &g_hbuf[p][l][0][0];
            const size_t wl = ((size_t)l * Hn + n) * In;
            const float* wzi = Wzi + wl;
            const float* wri = Wri + wl;
            const float* wgi = Wgi + wl;
            const float* wzh = Wzh + wl;
            const float* wrh = Wrh + wl;
            const float* wgh = Wgh + wl;

            ull acc[16];
#pragma unroll
            for (int i = 0; i < 16; ++i) acc[i] = 0ull;

            Stage s0 = ld_tile(srcI, strI, 0);
            st_tile(shTa, s0);
            __syncthreads();

            int buf = 0;
#pragma unroll 1
            for (int tt = 0; tt < 8; ++tt) {
                Stage nx;
                if (tt < 7) {
                    const float* nsrc = (tt + 1 < 4) ? srcI : srcH;
                    size_t nstr = (tt + 1 < 4) ? strI : (size_t)Hn;
                    nx = ld_tile(nsrc, nstr, ((tt + 1) & 3) * 256);
                }
                ull* shc = buf ? shTb : shTa;
                const int cb = (tt & 3) * 256;
                if (tt < 4)
                    compute3(shc, wzi + cb, wri + cb, wgi + cb, kh, bq,
                             acc + 0, acc + 4, acc + 8);
                else
                    compute3(shc, wzh + cb, wrh + cb, wgh + cb, kh, bq,
                             acc + 0, acc + 4, acc + 12);
                if (tt < 7) st_tile(buf ? shTa : shTb, nx);
                __syncthreads();
                buf ^= 1;
            }

            // cross-kh reduction
            if (kh > 0) {
                ull* d = shRed[(kh - 1) * 64 + slot];
#pragma unroll
                for (int i = 0; i < 16; ++i) d[i] = acc[i];
            }
            __syncthreads();
            if (kh == 0) {
#pragma unroll
                for (int j = 0; j < 7; ++j) {
                    ull* sr = shRed[j * 64 + slot];
#pragma unroll
                    for (int i = 0; i < 16; ++i) fadd2(acc[i], sr[i]);
                }
                const float bz = bzh[l * Hn + n];
                const float br = brh[l * Hn + n];
                const float bg = bgh[l * Hn + n];
#pragma unroll
                for (int b = 0; b < 4; ++b) {
                    const int gb = bq * 4 + b;
                    float za = hsum(acc[b]) + bz;
                    float ra = hsum(acc[4 + b]) + br;
                    float gi = hsum(acc[8 + b]);
                    float gh = hsum(acc[12 + b]) + bg;
                    float zv = 1.0f / (1.0f + expf(-za));
                    float rv = 1.0f / (1.0f + expf(-ra));
                    float gv = tanhf(gi + rv * gh);
                    float hold = g_hbuf[p][l][gb][n];
                    g_hbuf[q][l][gb][n] = zv * hold + (1.0f - zv) * gv;
                }
            }
            gsync();
        }

        // ---- output projection: out[b][t][:] = h2 @ Wout.T + bout ----
        {
            const float* srcO = &g_hbuf[q][Ln - 1][0][0];
            const float* wo = Wout + (size_t)n * Hn;
            ull ao[4] = {0ull, 0ull, 0ull, 0ull};

            Stage s0 = ld_tile(srcO, Hn, 0);
            st_tile(shTa, s0);
            __syncthreads();

            int buf = 0;
#pragma unroll 1
            for (int tt = 0; tt < 4; ++tt) {
                Stage nx;
                if (tt < 3) nx = ld_tile(srcO, Hn, (tt + 1) * 256);
                ull* shc = buf ? shTb : shTa;
                compute1(shc, wo + tt * 256, kh, bq, ao);
                if (tt < 3) st_tile(buf ? shTa : shTb, nx);
                __syncthreads();
                buf ^= 1;
            }

            if (kh > 0) {
                ull* d = shRed[(kh - 1) * 64 + slot];
#pragma unroll
                for (int i = 0; i < 4; ++i) d[i] = ao[i];
            }
            __syncthreads();
            if (kh == 0) {
#pragma unroll
                for (int j = 0; j < 7; ++j) {
                    ull* sr = shRed[j * 64 + slot];
#pragma unroll
                    for (int i = 0; i < 4; ++i) fadd2(ao[i], sr[i]);
                }
                const float bo = bout[n];
#pragma unroll
                for (int b = 0; b < 4; ++b) {
                    const int gb = bq * 4 + b;
                    out[((size_t)gb * Sn + t) * On + n] = hsum(ao[b]) + bo;
                }
            }
            // no gsync: next phase only re-reads buffers already fenced by the
            // per-layer gsyncs (see write/read distance analysis).
        }
        p = q;
    }

    gsync();
    // final hidden state
    const size_t base = (size_t)Bn * Sn * On;
    for (int i = blockIdx.x * NTHR + tid; i < Ln * Bn * Hn; i += NCTA * NTHR) {
        int hh = i % Hn;
        int b_ = (i / Hn) % Bn;
        int l_ = i / (Hn * Bn);
        out[base + ((size_t)b_ * Ln + l_) * Hn + hh] = g_hbuf[p][l_][b_][hh];
    }
}

extern "C" void kernel_launch(void* const* d_in, const int* in_sizes, int n_in,
                              void* d_out, int out_size) {
    const float* x    = (const float*)d_in[0];
    const float* h0   = (const float*)d_in[1];
    const float* Wzi  = (const float*)d_in[2];
    const float* Wzh  = (const float*)d_in[3];
    const float* bzh  = (const float*)d_in[4];
    const float* Wri  = (const float*)d_in[5];
    const float* Wrh  = (const float*)d_in[6];
    const float* brh  = (const float*)d_in[7];
    const float* Wgi  = (const float*)d_in[8];
    const float* Wgh  = (const float*)d_in[9];
    const float* bgh  = (const float*)d_in[10];
    const float* Wout = (const float*)d_in[11];
    const float* bout = (const float*)d_in[12];
    float* out = (float*)d_out;

    const int smem_bytes = (2 * 32 * PADR + 7 * 64 * 16) * (int)sizeof(ull);
    cudaFuncSetAttribute(gru_persistent,
                         cudaFuncAttributeMaxDynamicSharedMemorySize, smem_bytes);
    gru_persistent<<<NCTA, NTHR, smem_bytes>>>(x, h0, Wzi, Wzh, bzh, Wri, Wrh,
                                               brh, Wgi, Wgh, bgh, Wout, bout, out);
}

// round 3
// speedup vs baseline: 1.0001x; 1.0001x over previous
#include <cuda_runtime.h>

#define Bn 32
#define Sn 512
#define In 1024
#define Hn 1024
#define Ln 3
#define On 1024
#define NCTA 128
#define NTHR 512
#define PADR 130   // ull per 32-batch row in shared tile (pad keeps banks clean, 16B align)

typedef unsigned long long ull;

// Scratch: double-buffered hidden state per layer (rewritten from h0 every launch).
__device__ float g_hbuf[2][Ln][Bn][Hn];
__device__ unsigned g_cnt = 0;
__device__ unsigned g_gen = 0;

// ---------------- packed f32x2 helpers (pairing dimension = K) ----------------
__device__ __forceinline__ void fma2(ull& a, ull w, ull i) {
    asm("fma.rn.f32x2 %0, %1, %2, %0;" : "+l"(a) : "l"(w), "l"(i));
}
__device__ __forceinline__ void fadd2(ull& a, ull b) {
    asm("add.rn.f32x2 %0, %0, %1;" : "+l"(a) : "l"(b));
}
__device__ __forceinline__ float hsum(ull v) {
    float lo, hi;
    asm("mov.b64 {%0,%1}, %2;" : "=f"(lo), "=f"(hi) : "l"(v));
    return lo + hi;
}

// ---------------- software grid barrier ----------------
__device__ __forceinline__ void gsync() {
    __threadfence();
    __syncthreads();
    if (threadIdx.x == 0) {
        unsigned gen = *((volatile unsigned*)&g_gen);
        unsigned t = atomicAdd(&g_cnt, 1u);
        if (t == gridDim.x - 1) {
            g_cnt = 0;
            __threadfence();
            *((volatile unsigned*)&g_gen) = gen + 1;
        } else {
            while (*((volatile unsigned*)&g_gen) == gen) { }
        }
        __threadfence();
    }
    __syncthreads();
}

// ---------------- tile staging: LDG first, STS deferred (hides global latency) ----
struct Stage { float4 v[4]; };

__device__ __forceinline__ Stage ld_tile(const float* __restrict__ src,
                                         size_t stride, int col0) {
    Stage s;
    int tid = threadIdx.x;
#pragma unroll
    for (int r = 0; r < 4; ++r) {
        int u = tid + r * NTHR;
        int b = u >> 6;          // batch row 0..31
        int q = u & 63;          // float4 index within 256-float row slice
        s.v[r] = *reinterpret_cast<const float4*>(src + (size_t)b * stride + col0 + q * 4);
    }
    return s;
}

__device__ __forceinline__ void st_tile(ull* __restrict__ sh, const Stage& s) {
    int tid = threadIdx.x;
#pragma unroll
    for (int r = 0; r < 4; ++r) {
        int u = tid + r * NTHR;
        int b = u >> 6;
        int q = u & 63;
        *reinterpret_cast<float4*>(sh + b * PADR + q * 2) = s.v[r];
    }
}

// 3-gate accumulation over this thread's 32-k slice of a 256-k tile.
__device__ __forceinline__ void compute3(const ull* __restrict__ sh,
                                         const float* __restrict__ w0,
                                         const float* __restrict__ w1,
                                         const float* __restrict__ w2,
                                         int kh, int bq,
                                         ull* a0, ull* a1, ull* a2) {
    const int kbase = kh * 16;  // ull offset inside row
#pragma unroll
    for (int g = 0; g < 8; ++g) {
        const int kc = kh * 32 + g * 4;  // float offset inside tile
        ulonglong2 wz = *reinterpret_cast<const ulonglong2*>(w0 + kc);
        ulonglong2 wr = *reinterpret_cast<const ulonglong2*>(w1 + kc);
        ulonglong2 wg = *reinterpret_cast<const ulonglong2*>(w2 + kc);
#pragma unroll
        for (int b = 0; b < 4; ++b) {
            const ull* sp = sh + (bq * 4 + b) * PADR + kbase + g * 2;
            ull i0 = sp[0];
            ull i1 = sp[1];
            fma2(a0[b], wz.x, i0); fma2(a0[b], wz.y, i1);
            fma2(a1[b], wr.x, i0); fma2(a1[b], wr.y, i1);
            fma2(a2[b], wg.x, i0); fma2(a2[b], wg.y, i1);
        }
    }
}

__device__ __forceinline__ void compute1(const ull* __restrict__ sh,
                                         const float* __restrict__ w0,
                                         int kh, int bq, ull* a0) {
    const int kbase = kh * 16;
#pragma unroll
    for (int g = 0; g < 8; ++g) {
        const int kc = kh * 32 + g * 4;
        ulonglong2 wz = *reinterpret_cast<const ulonglong2*>(w0 + kc);
#pragma unroll
        for (int b = 0; b < 4; ++b) {
            const ull* sp = sh + (bq * 4 + b) * PADR + kbase + g * 2;
            ull i0 = sp[0];
            ull i1 = sp[1];
            fma2(a0[b], wz.x, i0); fma2(a0[b], wz.y, i1);
        }
    }
}

__global__ void __launch_bounds__(NTHR, 1)
gru_persistent(const float* __restrict__ x, const float* __restrict__ h0,
               const float* __restrict__ Wzi, const float* __restrict__ Wzh,
               const float* __restrict__ bzh, const float* __restrict__ Wri,
               const float* __restrict__ Wrh, const float* __restrict__ brh,
               const float* __restrict__ Wgi, const float* __restrict__ Wgh,
               const float* __restrict__ bgh, const float* __restrict__ Wout,
               const float* __restrict__ bout, float* __restrict__ out) {
    extern __shared__ ull smem[];
    ull* shTa = smem;                   // tile buffer 0: 32*PADR ull
    ull* shTb = smem + 32 * PADR;       // tile buffer 1
    ull (*shRed)[16] = reinterpret_cast<ull(*)[16]>(smem + 2 * 32 * PADR);  // [7*64][16]

    const int tid = threadIdx.x;
    const int ns = tid & 7;            // n slot (8 per CTA)
    const int bq = (tid >> 3) & 7;     // batch quad: batches bq*4 .. bq*4+3
    const int kh = tid >> 6;           // k-split group (8): 32 k per 256-k tile
    const int slot = tid & 63;         // (bq, ns) output slot
    const int n = blockIdx.x * 8 + ns; // output column

    // init hidden buffer 0 from h0 (B, L, H)
    for (int i = blockIdx.x * NTHR + tid; i < Ln * Bn * Hn; i += NCTA * NTHR) {
        int hh = i % Hn;
        int b_ = (i / Hn) % Bn;
        int l_ = i / (Hn * Bn);
        g_hbuf[0][l_][b_][hh] = h0[((size_t)b_ * Ln + l_) * Hn + hh];
    }
    gsync();

    int p = 0;
#pragma unroll 1
    for (int t = 0; t < Sn; ++t) {
        const int q = p ^ 1;
#pragma unroll 1
        for (int l = 0; l < Ln; ++l) {
            const float* srcI = (l == 0) ? (x + (size_t)t * In)
                                         : &g_hbuf[q][l - 1][0][0];
            const size_t strI = (l == 0) ? (size_t)Sn * In : (size_t)Hn;
            const float* srcH = &g_hbuf[p][l][0][0];
            const size_t wl = ((size_t)l * Hn + n) * In;
            const float* wzi = Wzi + wl;
            const float* wri = Wri + wl;
            const float* wgi = Wgi + wl;
            const float* wzh = Wzh + wl;
            const float* wrh = Wrh + wl;
            const float* wgh = Wgh + wl;

            ull acc[16];
#pragma unroll
            for (int i = 0; i < 16; ++i) acc[i] = 0ull;

            Stage s0 = ld_tile(srcI, strI, 0);
            st_tile(shTa, s0);
            __syncthreads();

            int buf = 0;
#pragma unroll 1
            for (int tt = 0; tt < 8; ++tt) {
                Stage nx;
                if (tt < 7) {
                    const float* nsrc = (tt + 1 < 4) ? srcI : srcH;
                    size_t nstr = (tt + 1 < 4) ? strI : (size_t)Hn;
                    nx = ld_tile(nsrc, nstr, ((tt + 1) & 3) * 256);
                }
                ull* shc = buf ? shTb : shTa;
                const int cb = (tt & 3) * 256;
                if (tt < 4)
                    compute3(shc, wzi + cb, wri + cb, wgi + cb, kh, bq,
                             acc + 0, acc + 4, acc + 8);
                else
                    compute3(shc, wzh + cb, wrh + cb, wgh + cb, kh, bq,
                             acc + 0, acc + 4, acc + 12);
                if (tt < 7) st_tile(buf ? shTa : shTb, nx);
                __syncthreads();
                buf ^= 1;
            }

            // cross-kh reduction
            if (kh > 0) {
                ull* d = shRed[(kh - 1) * 64 + slot];
#pragma unroll
                for (int i = 0; i < 16; ++i) d[i] = acc[i];
            }
            __syncthreads();
            if (kh == 0) {
#pragma unroll
                for (int j = 0; j < 7; ++j) {
                    ull* sr = shRed[j * 64 + slot];
#pragma unroll
                    for (int i = 0; i < 16; ++i) fadd2(acc[i], sr[i]);
                }
                const float bz = bzh[l * Hn + n];
                const float br = brh[l * Hn + n];
                const float bg = bgh[l * Hn + n];
#pragma unroll
                for (int b = 0; b < 4; ++b) {
                    const int gb = bq * 4 + b;
                    float za = hsum(acc[b]) + bz;
                    float ra = hsum(acc[4 + b]) + br;
                    float gi = hsum(acc[8 + b]);
                    float gh = hsum(acc[12 + b]) + bg;
                    float zv = 1.0f / (1.0f + expf(-za));
                    float rv = 1.0f / (1.0f + expf(-ra));
                    float gv = tanhf(gi + rv * gh);
                    float hold = g_hbuf[p][l][gb][n];
                    g_hbuf[q][l][gb][n] = zv * hold + (1.0f - zv) * gv;
                }
            }
            gsync();
        }

        // ---- output projection: out[b][t][:] = h2 @ Wout.T + bout ----
        {
            const float* srcO = &g_hbuf[q][Ln - 1][0][0];
            const float* wo = Wout + (size_t)n * Hn;
            ull ao[4] = {0ull, 0ull, 0ull, 0ull};

            Stage s0 = ld_tile(srcO, Hn, 0);
            st_tile(shTa, s0);
            __syncthreads();

            int buf = 0;
#pragma unroll 1
            for (int tt = 0; tt < 4; ++tt) {
                Stage nx;
                if (tt < 3) nx = ld_tile(srcO, Hn, (tt + 1) * 256);
                ull* shc = buf ? shTb : shTa;
                compute1(shc, wo + tt * 256, kh, bq, ao);
                if (tt < 3) st_tile(buf ? shTa : shTb, nx);
                __syncthreads();
                buf ^= 1;
            }

            if (kh > 0) {
                ull* d = shRed[(kh - 1) * 64 + slot];
#pragma unroll
                for (int i = 0; i < 4; ++i) d[i] = ao[i];
            }
            __syncthreads();
            if (kh == 0) {
#pragma unroll
                for (int j = 0; j < 7; ++j) {
                    ull* sr = shRed[j * 64 + slot];
#pragma unroll
                    for (int i = 0; i < 4; ++i) fadd2(ao[i], sr[i]);
                }
                const float bo = bout[n];
#pragma unroll
                for (int b = 0; b < 4; ++b) {
                    const int gb = bq * 4 + b;
                    out[((size_t)gb * Sn + t) * On + n] = hsum(ao[b]) + bo;
                }
            }
            // no gsync: next phase only re-reads buffers already fenced by the
            // per-layer gsyncs (see write/read distance analysis).
        }
        p = q;
    }

    gsync();
    // final hidden state
    const size_t base = (size_t)Bn * Sn * On;
    for (int i = blockIdx.x * NTHR + tid; i < Ln * Bn * Hn; i += NCTA * NTHR) {
        int hh = i % Hn;
        int b_ = (i / Hn) % Bn;
        int l_ = i / (Hn * Bn);
        out[base + ((size_t)b_ * Ln + l_) * Hn + hh] = g_hbuf[p][l_][b_][hh];
    }
}

extern "C" void kernel_launch(void* const* d_in, const int* in_sizes, int n_in,
                              void* d_out, int out_size) {
    const float* x    = (const float*)d_in[0];
    const float* h0   = (const float*)d_in[1];
    const float* Wzi  = (const float*)d_in[2];
    const float* Wzh  = (const float*)d_in[3];
    const float* bzh  = (const float*)d_in[4];
    const float* Wri  = (const float*)d_in[5];
    const float* Wrh  = (const float*)d_in[6];
    const float* brh  = (const float*)d_in[7];
    const float* Wgi  = (const float*)d_in[8];
    const float* Wgh  = (const float*)d_in[9];
    const float* bgh  = (const float*)d_in[10];
    const float* Wout = (const float*)d_in[11];
    const float* bout = (const float*)d_in[12];
    float* out = (float*)d_out;

    const int smem_bytes = (2 * 32 * PADR + 7 * 64 * 16) * (int)sizeof(ull);
    cudaFuncSetAttribute(gru_persistent,
                         cudaFuncAttributeMaxDynamicSharedMemorySize, smem_bytes);
    gru_persistent<<<NCTA, NTHR, smem_bytes>>>(x, h0, Wzi, Wzh, bzh, Wri, Wrh,
                                               brh, Wgi, Wgh, bgh, Wout, bout, out);
}

// round 5
// speedup vs baseline: 3.8244x; 3.8241x over previous
#include <cuda_runtime.h>
#include <cuda_bf16.h>

#define NCTA 112
#define NTHR 256
#define GT (NCTA * NTHR)
typedef unsigned int u32;

// Weights pre-packed in mma fragment order, bf16 hi/lo.
// gates: (l*96+u)*131072 shorts; unit = [hi 65536][lo 65536]
// out:   37748736 + u*131072, 16 units
__device__ __align__(16) unsigned short g_w[39845888];
__device__ __align__(16) unsigned short g_xt[33554432]; // x B-frags per t (65536 shorts)
__device__ __align__(16) unsigned short g_bh[3][65536]; // h B-frags per layer
__device__ __align__(16) float g_part[112 * 4096];      // [unit][row][b]
__device__ float g_hfp[3][1024][32];                    // fp32 hidden [l][n][b]
__device__ unsigned g_cnt = 0, g_gen = 0;

static __device__ __forceinline__ void gsync() {
    __threadfence();
    __syncthreads();
    if (threadIdx.x == 0) {
        unsigned gen = *((volatile unsigned*)&g_gen);
        unsigned t = atomicAdd(&g_cnt, 1u);
        if (t == gridDim.x - 1) {
            g_cnt = 0;
            __threadfence();
            *((volatile unsigned*)&g_gen) = gen + 1;
        } else {
            while (*((volatile unsigned*)&g_gen) == gen) { }
        }
        __threadfence();
    }
    __syncthreads();
}
static __device__ __forceinline__ void hilo(float v, unsigned short& h,
                                            unsigned short& l) {
    __nv_bfloat16 hb = __float2bfloat16(v);
    __nv_bfloat16 lb = __float2bfloat16(v - __bfloat162float(hb));
    h = *(unsigned short*)&hb;
    l = *(unsigned short*)&lb;
}
static __device__ __forceinline__ void mma16816(float* c, uint4 a, u32 b0, u32 b1) {
    asm volatile(
        "mma.sync.aligned.m16n8k16.row.col.f32.bf16.bf16.f32 "
        "{%0,%1,%2,%3}, {%4,%5,%6,%7}, {%8,%9}, {%0,%1,%2,%3};"
        : "+f"(c[0]), "+f"(c[1]), "+f"(c[2]), "+f"(c[3])
        : "r"(a.x), "r"(a.y), "r"(a.z), "r"(a.w), "r"(b0), "r"(b1));
}
// A-fragment short index for element (r,c) in a 16x16 tile (lane-major packing)
static __device__ __forceinline__ int a_idx(int r, int c) {
    int lane = (r & 7) * 4 + ((c & 7) >> 1);
    int j = (r >> 3) + ((c >> 3) << 1);
    return lane * 8 + j * 2 + (c & 1);
}
// B-fragment short index for element (k 0..511, b 0..31) within one khalf block
static __device__ __forceinline__ int b_idx(int k, int b) {
    int ks = k >> 4, kk = k & 15, nt = b >> 3, bn = b & 7;
    int lane = bn * 4 + ((kk & 7) >> 1);
    int s = ((kk >> 3) << 1) + (kk & 1);
    return ((ks * 32 + lane) * 2 + (nt >> 1)) * 8 + (nt & 1) * 4 + s;
}
static __device__ __forceinline__ void act_store(unsigned short* blkbase, int k,
                                                 int b, float v) {
    int i = b_idx(k, b);
    hilo(v, blkbase[i], blkbase[16384 + i]);
}

// [128 x 32 x 512] compensated-bf16 GEMM, pure LDG+HMMA.
static __device__ void unit_gemm(const unsigned short* __restrict__ wu,
                                 const unsigned short* __restrict__ bs,
                                 float* __restrict__ pdst) {
    const int tid = threadIdx.x, w = tid >> 5, lane = tid & 31;
    const uint4* A = (const uint4*)wu + w * 1024 + lane;  // + ks*32 ; lo at +8192
    const uint4* B = (const uint4*)bs + lane * 2;         // + ks*64 ; lo at +2048
    float acc[16];
#pragma unroll
    for (int i = 0; i < 16; ++i) acc[i] = 0.f;
    uint4 ah = A[0], al = A[8192];
    uint4 bh0 = B[0], bh1 = B[1], bl0 = B[2048], bl1 = B[2049];
#pragma unroll 2
    for (int ks = 0; ks < 32; ++ks) {
        uint4 nah, nal, nbh0, nbh1, nbl0, nbl1;
        if (ks < 31) {
            int o = (ks + 1) * 32, p = (ks + 1) * 64;
            nah = A[o]; nal = A[8192 + o];
            nbh0 = B[p]; nbh1 = B[p + 1];
            nbl0 = B[2048 + p]; nbl1 = B[2048 + p + 1];
        }
        mma16816(acc + 0, ah, bh0.x, bh0.y);
        mma16816(acc + 4, ah, bh0.z, bh0.w);
        mma16816(acc + 8, ah, bh1.x, bh1.y);
        mma16816(acc + 12, ah, bh1.z, bh1.w);
        mma16816(acc + 0, ah, bl0.x, bl0.y);
        mma16816(acc + 4, ah, bl0.z, bl0.w);
        mma16816(acc + 8, ah, bl1.x, bl1.y);
        mma16816(acc + 12, ah, bl1.z, bl1.w);
        mma16816(acc + 0, al, bh0.x, bh0.y);
        mma16816(acc + 4, al, bh0.z, bh0.w);
        mma16816(acc + 8, al, bh1.x, bh1.y);
        mma16816(acc + 12, al, bh1.z, bh1.w);
        ah = nah; al = nal; bh0 = nbh0; bh1 = nbh1; bl0 = nbl0; bl1 = nbl1;
    }
    const int r0 = w * 16 + (lane >> 2), cb = (lane & 3) * 2;
#pragma unroll
    for (int nt = 0; nt < 4; ++nt) {
        *(float2*)(pdst + r0 * 32 + nt * 8 + cb) = make_float2(acc[nt * 4], acc[nt * 4 + 1]);
        *(float2*)(pdst + (r0 + 8) * 32 + nt * 8 + cb) = make_float2(acc[nt * 4 + 2], acc[nt * 4 + 3]);
    }
}

__global__ void __launch_bounds__(NTHR, 1)
gru_tc(const float* __restrict__ x, const float* __restrict__ h0,
       const float* __restrict__ Wzi, const float* __restrict__ Wzh,
       const float* __restrict__ bzh, const float* __restrict__ Wri,
       const float* __restrict__ Wrh, const float* __restrict__ brh,
       const float* __restrict__ Wgi, const float* __restrict__ Wgh,
       const float* __restrict__ bgh, const float* __restrict__ Wout,
       const float* __restrict__ bout, float* __restrict__ out) {
    const int tid = threadIdx.x, cta = blockIdx.x, gtid = cta * NTHR + tid;

    // ---- init: pack weights into fragment order (hi/lo) ----
    const float* gm[6] = {Wzi, Wzh, Wri, Wrh, Wgi, Wgh};
    for (long e = gtid; e < 18874368L; e += GT) {
        int m = (int)(e / 3145728);
        long rem = e - (long)m * 3145728;
        int l = (int)(rem >> 20), j = (int)(rem & 1048575);
        int n = j >> 10, k = j & 1023;
        int u = (n >> 7) * 12 + m * 2 + (k >> 9);
        int k5 = k & 511, w = (n >> 4) & 7;
        long base = ((long)l * 96 + u) * 131072;
        int idx = ((w * 32 + (k5 >> 4)) * 32) * 8 + a_idx(n & 15, k5 & 15);
        hilo(gm[m][(long)l * 1048576 + j], g_w[base + idx], g_w[base + 65536 + idx]);
    }
    for (long e = gtid; e < 1048576L; e += GT) {
        int n = (int)(e >> 10), k = (int)(e & 1023);
        int u = (n >> 7) * 2 + (k >> 9);
        int k5 = k & 511, w = (n >> 4) & 7;
        long base = 37748736L + (long)u * 131072;
        int idx = ((w * 32 + (k5 >> 4)) * 32) * 8 + a_idx(n & 15, k5 & 15);
        hilo(Wout[e], g_w[base + idx], g_w[base + 65536 + idx]);
    }
    for (long e = gtid; e < 16777216L; e += GT) {
        int b = (int)(e >> 19), t = (int)((e >> 10) & 511), k = (int)(e & 1023);
        act_store(g_xt + (long)t * 65536 + (k >> 9) * 32768, k & 511, b, x[e]);
    }
    for (int e = gtid; e < 98304; e += GT) {
        int l = e / 32768, i = e & 32767, b = i >> 10, h = i & 1023;
        float v = h0[((long)b * 3 + l) * 1024 + h];
        g_hfp[l][h][b] = v;
        act_store(g_bh[l] + (h >> 9) * 32768, h & 511, b, v);
    }
    gsync();

#pragma unroll 1
    for (int t = 0; t < 512; ++t) {
#pragma unroll 1
        for (int l = 0; l < 3; ++l) {
            if (cta < 96) {
                int s = cta % 12, m = s >> 1, kh = s & 1;
                const unsigned short* bs =
                    (m & 1) ? g_bh[l] : (l == 0 ? g_xt + (long)t * 65536 : g_bh[l - 1]);
                unit_gemm(g_w + ((long)l * 96 + cta) * 131072, bs + kh * 32768,
                          g_part + cta * 4096);
            } else if (l == 0 && t > 0) {
                int j = cta - 96;
                unit_gemm(g_w + 37748736L + (long)j * 131072,
                          g_bh[2] + (j & 1) * 32768, g_part + (96 + j) * 4096);
            }
            gsync();
            for (int i = gtid; i < 32768; i += GT) {
                int n = i >> 5, b = i & 31, blk = n >> 7, nl = n & 127;
                const float* P = g_part + (long)blk * 12 * 4096 + nl * 32 + b;
                float zs = P[0] + P[4096] + P[8192] + P[12288];
                float rs = P[16384] + P[20480] + P[24576] + P[28672];
                float gi = P[32768] + P[36864];
                float gh = P[40960] + P[45056];
                float z = 1.f / (1.f + expf(-(zs + bzh[l * 1024 + n])));
                float r = 1.f / (1.f + expf(-(rs + brh[l * 1024 + n])));
                float g = tanhf(gi + r * (gh + bgh[l * 1024 + n]));
                float hn = z * g_hfp[l][n][b] + (1.f - z) * g;
                g_hfp[l][n][b] = hn;
                act_store(g_bh[l] + (n >> 9) * 32768, n & 511, b, hn);
            }
            if (l == 0 && t > 0) {
                for (int i = gtid; i < 32768; i += GT) {
                    int n = i >> 5, b = i & 31, nb = n >> 7, nl = n & 127;
                    const float* P = g_part + (96 + nb * 2) * 4096 + nl * 32 + b;
                    out[((long)b * 512 + (t - 1)) * 1024 + n] = P[0] + P[4096] + bout[n];
                }
            }
            gsync();
        }
    }
    if (cta >= 96) {
        int j = cta - 96;
        unit_gemm(g_w + 37748736L + (long)j * 131072, g_bh[2] + (j & 1) * 32768,
                  g_part + (96 + j) * 4096);
    }
    gsync();
    for (int i = gtid; i < 32768; i += GT) {
        int n = i >> 5, b = i & 31, nb = n >> 7, nl = n & 127;
        const float* P = g_part + (96 + nb * 2) * 4096 + nl * 32 + b;
        out[((long)b * 512 + 511) * 1024 + n] = P[0] + P[4096] + bout[n];
    }
    for (int e = gtid; e < 98304; e += GT) {
        int l = e / 32768, i = e & 32767, b = i >> 10, h = i & 1023;
        out[16777216L + ((long)b * 3 + l) * 1024 + h] = g_hfp[l][h][b];
    }
}

extern "C" void kernel_launch(void* const* d_in, const int* in_sizes, int n_in,
                              void* d_out, int out_size) {
    gru_tc<<<NCTA, NTHR>>>(
        (const float*)d_in[0], (const float*)d_in[1], (const float*)d_in[2],
        (const float*)d_in[3], (const float*)d_in[4], (const float*)d_in[5],
        (const float*)d_in[6], (const float*)d_in[7], (const float*)d_in[8],
        (const float*)d_in[9], (const float*)d_in[10], (const float*)d_in[11],
        (const float*)d_in[12], (float*)d_out);
}